// round 1
// baseline (speedup 1.0000x reference)
#include <cuda_runtime.h>
#include <math.h>

// Problem constants
#define BB 4
#define TT 2048
#define CC 1024
#define NH 16
#define HD 64
#define M1 (BB*TT)          // 8192
#define N_QKV (3*CC)        // 3072

// Scratch (device globals; allocation-free rule)
__device__ float g_q[BB*NH*TT*HD];     // [B,H,T,hd]
__device__ float g_k[BB*NH*TT*HD];
__device__ float g_v[BB*NH*TT*HD];
__device__ float g_attn[M1*CC];        // [B*T, C]

// ---------------------------------------------------------------------------
// GEMM 1: qkv = x @ w_attn + b_attn, scattered into g_q/g_k/g_v [B,H,T,hd]
// Tiles: BM=64, BN=64, BK=16; 256 threads; 4x4 per-thread microtile.
// ---------------------------------------------------------------------------
__global__ __launch_bounds__(256) void qkv_gemm(const float* __restrict__ x,
                                                const float* __restrict__ w,
                                                const float* __restrict__ bias)
{
    __shared__ float As[16][68];   // [k][m], padded
    __shared__ float Bs[16][64];   // [k][n]
    const int K = CC, N = N_QKV;
    const int n0 = blockIdx.x * 64;
    const int m0 = blockIdx.y * 64;
    const int t  = threadIdx.x;
    const int tx = t & 15, ty = t >> 4;
    const int am  = t >> 2, ak4 = (t & 3) * 4;
    const int bk  = t >> 4, bn4 = (t & 15) * 4;

    float acc[4][4];
    #pragma unroll
    for (int i = 0; i < 4; i++)
        #pragma unroll
        for (int j = 0; j < 4; j++) acc[i][j] = 0.f;

    for (int k0 = 0; k0 < K; k0 += 16) {
        float4 a = *(const float4*)&x[(size_t)(m0 + am) * K + k0 + ak4];
        As[ak4 + 0][am] = a.x;
        As[ak4 + 1][am] = a.y;
        As[ak4 + 2][am] = a.z;
        As[ak4 + 3][am] = a.w;
        *(float4*)&Bs[bk][bn4] = *(const float4*)&w[(size_t)(k0 + bk) * N + n0 + bn4];
        __syncthreads();
        #pragma unroll
        for (int k = 0; k < 16; k++) {
            float4 av = *(float4*)&As[k][ty * 4];
            float4 bv = *(float4*)&Bs[k][tx * 4];
            float aa[4] = {av.x, av.y, av.z, av.w};
            float bb[4] = {bv.x, bv.y, bv.z, bv.w};
            #pragma unroll
            for (int i = 0; i < 4; i++)
                #pragma unroll
                for (int j = 0; j < 4; j++)
                    acc[i][j] = fmaf(aa[i], bb[j], acc[i][j]);
        }
        __syncthreads();
    }

    #pragma unroll
    for (int i = 0; i < 4; i++) {
        int m = m0 + ty * 4 + i;
        int b  = m >> 11;          // /2048
        int tt = m & 2047;
        #pragma unroll
        for (int j = 0; j < 4; j++) {
            int n = n0 + tx * 4 + j;
            float v = acc[i][j] + bias[n];
            int which = n >> 10;       // 0=q 1=k 2=v
            int c = n & 1023;
            int h = c >> 6;
            int d = c & 63;
            float* dst = (which == 0) ? g_q : (which == 1) ? g_k : g_v;
            dst[(((size_t)(b * NH + h)) * TT + tt) * HD + d] = v;
        }
    }
}

// ---------------------------------------------------------------------------
// Flash attention (fp32, causal, online softmax).
// Block = one (b, h, 64-row q-tile); 256 threads; quad of threads per q-row.
// Thread (r = t>>2, c = t&3): computes S[r, c+4j] (j=0..15, strided cols),
// and accumulates O[r, c*16 .. c*16+15] via smem-staged P.
// ---------------------------------------------------------------------------
__global__ __launch_bounds__(256) void flash_kernel()
{
    extern __shared__ float sm[];
    float* Qs = sm;                 // 64 x 68
    float* Ks = Qs + 64 * 68;       // 64 x 68
    float* Vs = Ks + 64 * 68;       // 64 x 64 (no pad: broadcast reads)
    float* Ps = Vs + 64 * 64;       // 64 x 68

    const int qt = (int)gridDim.x - 1 - (int)blockIdx.x;  // heavy tiles first
    const int h  = blockIdx.y;
    const int b  = blockIdx.z;
    const int t  = threadIdx.x;
    const int r  = t >> 2;
    const int c  = t & 3;

    const size_t head_off = ((size_t)(b * NH + h)) * TT * HD;
    const float* Qg = g_q + head_off;
    const float* Kg = g_k + head_off;
    const float* Vg = g_v + head_off;
    const int q0 = qt * 64;

    // Load Q tile, pre-scaled by 1/sqrt(64)
    for (int i = t; i < 64 * 16; i += 256) {
        int row = i >> 4, d4 = i & 15;
        float4 qv = *(const float4*)&Qg[(size_t)(q0 + row) * HD + d4 * 4];
        qv.x *= 0.125f; qv.y *= 0.125f; qv.z *= 0.125f; qv.w *= 0.125f;
        *(float4*)&Qs[row * 68 + d4 * 4] = qv;
    }

    float m_run = -1e30f, l_run = 0.f;
    float4 o[4];
    #pragma unroll
    for (int i = 0; i < 4; i++) { o[i].x = 0.f; o[i].y = 0.f; o[i].z = 0.f; o[i].w = 0.f; }

    for (int kt = 0; kt <= qt; kt++) {
        __syncthreads();   // previous iter's K/V/P reads done
        const int k0 = kt * 64;
        for (int i = t; i < 64 * 16; i += 256) {
            int row = i >> 4, d4 = i & 15;
            *(float4*)&Ks[row * 68 + d4 * 4] =
                *(const float4*)&Kg[(size_t)(k0 + row) * HD + d4 * 4];
            *(float4*)&Vs[row * 64 + d4 * 4] =
                *(const float4*)&Vg[(size_t)(k0 + row) * HD + d4 * 4];
        }
        __syncthreads();

        // S = Q K^T  (thread: s[j] = S[r, c+4j])
        float s[16];
        #pragma unroll
        for (int j = 0; j < 16; j++) s[j] = 0.f;
        #pragma unroll
        for (int d4 = 0; d4 < 16; d4++) {
            float4 qv = *(float4*)&Qs[r * 68 + d4 * 4];
            #pragma unroll
            for (int j = 0; j < 16; j++) {
                float4 kv = *(float4*)&Ks[(c + 4 * j) * 68 + d4 * 4];
                s[j] = fmaf(qv.x, kv.x, s[j]);
                s[j] = fmaf(qv.y, kv.y, s[j]);
                s[j] = fmaf(qv.z, kv.z, s[j]);
                s[j] = fmaf(qv.w, kv.w, s[j]);
            }
        }

        if (kt == qt) {
            #pragma unroll
            for (int j = 0; j < 16; j++) {
                int kg = k0 + c + 4 * j;
                if (kg > q0 + r) s[j] = -1e30f;
            }
        }

        // Online softmax (quad-level reductions; quad lanes share a warp)
        float mloc = s[0];
        #pragma unroll
        for (int j = 1; j < 16; j++) mloc = fmaxf(mloc, s[j]);
        mloc = fmaxf(mloc, __shfl_xor_sync(0xffffffffu, mloc, 1));
        mloc = fmaxf(mloc, __shfl_xor_sync(0xffffffffu, mloc, 2));
        float m_new = fmaxf(m_run, mloc);
        float alpha = __expf(m_run - m_new);
        float lloc = 0.f;
        #pragma unroll
        for (int j = 0; j < 16; j++) {
            s[j] = __expf(s[j] - m_new);
            lloc += s[j];
        }
        lloc += __shfl_xor_sync(0xffffffffu, lloc, 1);
        lloc += __shfl_xor_sync(0xffffffffu, lloc, 2);
        l_run = l_run * alpha + lloc;
        m_run = m_new;
        #pragma unroll
        for (int i = 0; i < 4; i++) {
            o[i].x *= alpha; o[i].y *= alpha; o[i].z *= alpha; o[i].w *= alpha;
        }

        // Stage P (strided cols; conflict-free writes with pad 68)
        #pragma unroll
        for (int j = 0; j < 16; j++) Ps[r * 68 + c + 4 * j] = s[j];
        __syncthreads();

        // O += P V  (thread reads full P row; V rows broadcast across warp)
        #pragma unroll 8
        for (int k = 0; k < 64; k++) {
            float p = Ps[r * 68 + k];
            #pragma unroll
            for (int dd = 0; dd < 4; dd++) {
                float4 vv = *(float4*)&Vs[k * 64 + (c * 4 + dd) * 4];
                o[dd].x = fmaf(p, vv.x, o[dd].x);
                o[dd].y = fmaf(p, vv.y, o[dd].y);
                o[dd].z = fmaf(p, vv.z, o[dd].z);
                o[dd].w = fmaf(p, vv.w, o[dd].w);
            }
        }
    }

    const float inv = 1.f / l_run;
    const int out_row = b * TT + q0 + r;
    const int colbase = h * HD + c * 16;
    #pragma unroll
    for (int dd = 0; dd < 4; dd++) {
        o[dd].x *= inv; o[dd].y *= inv; o[dd].z *= inv; o[dd].w *= inv;
        *(float4*)&g_attn[(size_t)out_row * CC + colbase + dd * 4] = o[dd];
    }
}

// ---------------------------------------------------------------------------
// GEMM 2: out = attn @ w_proj + b_proj
// ---------------------------------------------------------------------------
__global__ __launch_bounds__(256) void proj_gemm(const float* __restrict__ w,
                                                 const float* __restrict__ bias,
                                                 float* __restrict__ out)
{
    __shared__ float As[16][68];
    __shared__ float Bs[16][64];
    const int K = CC, N = CC;
    const int n0 = blockIdx.x * 64;
    const int m0 = blockIdx.y * 64;
    const int t  = threadIdx.x;
    const int tx = t & 15, ty = t >> 4;
    const int am  = t >> 2, ak4 = (t & 3) * 4;
    const int bk  = t >> 4, bn4 = (t & 15) * 4;

    float acc[4][4];
    #pragma unroll
    for (int i = 0; i < 4; i++)
        #pragma unroll
        for (int j = 0; j < 4; j++) acc[i][j] = 0.f;

    for (int k0 = 0; k0 < K; k0 += 16) {
        float4 a = *(const float4*)&g_attn[(size_t)(m0 + am) * K + k0 + ak4];
        As[ak4 + 0][am] = a.x;
        As[ak4 + 1][am] = a.y;
        As[ak4 + 2][am] = a.z;
        As[ak4 + 3][am] = a.w;
        *(float4*)&Bs[bk][bn4] = *(const float4*)&w[(size_t)(k0 + bk) * N + n0 + bn4];
        __syncthreads();
        #pragma unroll
        for (int k = 0; k < 16; k++) {
            float4 av = *(float4*)&As[k][ty * 4];
            float4 bv = *(float4*)&Bs[k][tx * 4];
            float aa[4] = {av.x, av.y, av.z, av.w};
            float bb[4] = {bv.x, bv.y, bv.z, bv.w};
            #pragma unroll
            for (int i = 0; i < 4; i++)
                #pragma unroll
                for (int j = 0; j < 4; j++)
                    acc[i][j] = fmaf(aa[i], bb[j], acc[i][j]);
        }
        __syncthreads();
    }

    #pragma unroll
    for (int i = 0; i < 4; i++) {
        int m = m0 + ty * 4 + i;
        #pragma unroll
        for (int j = 0; j < 4; j++) {
            int n = n0 + tx * 4 + j;
            out[(size_t)m * N + n] = acc[i][j] + bias[n];
        }
    }
}

extern "C" void kernel_launch(void* const* d_in, const int* in_sizes, int n_in,
                              void* d_out, int out_size)
{
    const float* x      = (const float*)d_in[0];
    const float* w_attn = (const float*)d_in[1];
    const float* b_attn = (const float*)d_in[2];
    const float* w_proj = (const float*)d_in[3];
    const float* b_proj = (const float*)d_in[4];
    float* out = (float*)d_out;

    dim3 g1(N_QKV / 64, M1 / 64);
    qkv_gemm<<<g1, 256>>>(x, w_attn, b_attn);

    const int flash_smem = (64 * 68 * 3 + 64 * 64) * (int)sizeof(float);  // 68608 B
    cudaFuncSetAttribute(flash_kernel, cudaFuncAttributeMaxDynamicSharedMemorySize,
                         flash_smem);
    dim3 g2(TT / 64, NH, BB);
    flash_kernel<<<g2, 256, flash_smem>>>();

    dim3 g3(CC / 64, M1 / 64);
    proj_gemm<<<g3, 256>>>(w_proj, b_proj, out);
}

// round 3
// speedup vs baseline: 4.4752x; 4.4752x over previous
#include <cuda_runtime.h>
#include <cuda_bf16.h>
#include <cstdint>
#include <math.h>

#define BB 4
#define TT 2048
#define CC 1024
#define NH 16
#define HD 64
#define M1 (BB*TT)          // 8192
#define N_QKV (3*CC)        // 3072

// ---------------------------------------------------------------------------
// Device-global scratch (allocation-free rule)
// ---------------------------------------------------------------------------
__device__ __nv_bfloat16 g_xhi[M1*CC], g_xlo[M1*CC];        // x [M,K]
__device__ __nv_bfloat16 g_wqh[N_QKV*CC], g_wql[N_QKV*CC];  // w_attn^T [N,K]
__device__ __nv_bfloat16 g_wph[CC*CC], g_wpl[CC*CC];        // w_proj^T [N,K]
__device__ __nv_bfloat16 g_qh[BB*NH*TT*HD], g_ql[BB*NH*TT*HD];
__device__ __nv_bfloat16 g_kh[BB*NH*TT*HD], g_kl[BB*NH*TT*HD];
__device__ __nv_bfloat16 g_vh[BB*NH*TT*HD], g_vl[BB*NH*TT*HD];
__device__ __nv_bfloat16 g_ahi[M1*CC], g_alo[M1*CC];        // attn out [M,C]

// ---------------------------------------------------------------------------
// PTX helpers (baseline ISA only: ldmatrix / mma.sync / cp.async)
// ---------------------------------------------------------------------------
__device__ __forceinline__ uint32_t smem_u32(const void* p) {
    uint32_t a;
    asm("{ .reg .u64 t; cvta.to.shared.u64 t, %1; cvt.u32.u64 %0, t; }"
        : "=r"(a) : "l"(p));
    return a;
}
__device__ __forceinline__ void cpasync16(uint32_t dst, const void* src) {
    asm volatile("cp.async.cg.shared.global [%0], [%1], 16;"
                 :: "r"(dst), "l"(src) : "memory");
}
#define CP_COMMIT() asm volatile("cp.async.commit_group;" ::: "memory")
#define CP_WAIT(N)  asm volatile("cp.async.wait_group %0;" :: "n"(N) : "memory")

__device__ __forceinline__ void ldsm4(uint32_t& r0, uint32_t& r1, uint32_t& r2,
                                      uint32_t& r3, uint32_t a) {
    asm volatile("ldmatrix.sync.aligned.m8n8.x4.shared.b16 {%0,%1,%2,%3},[%4];"
                 : "=r"(r0), "=r"(r1), "=r"(r2), "=r"(r3) : "r"(a));
}
__device__ __forceinline__ void ldsm4t(uint32_t& r0, uint32_t& r1, uint32_t& r2,
                                       uint32_t& r3, uint32_t a) {
    asm volatile("ldmatrix.sync.aligned.m8n8.x4.trans.shared.b16 {%0,%1,%2,%3},[%4];"
                 : "=r"(r0), "=r"(r1), "=r"(r2), "=r"(r3) : "r"(a));
}
__device__ __forceinline__ void mma16816(float* c, const uint32_t* a,
                                         uint32_t b0, uint32_t b1) {
    asm volatile("mma.sync.aligned.m16n8k16.row.col.f32.bf16.bf16.f32 "
                 "{%0,%1,%2,%3},{%4,%5,%6,%7},{%8,%9},{%0,%1,%2,%3};"
                 : "+f"(c[0]), "+f"(c[1]), "+f"(c[2]), "+f"(c[3])
                 : "r"(a[0]), "r"(a[1]), "r"(a[2]), "r"(a[3]), "r"(b0), "r"(b1));
}

__device__ __forceinline__ void split_pair(float x0, float x1,
                                           uint32_t& hi, uint32_t& lo) {
    __nv_bfloat16 h0 = __float2bfloat16(x0), h1 = __float2bfloat16(x1);
    __nv_bfloat162 hp = __halves2bfloat162(h0, h1);
    __nv_bfloat162 lp = __halves2bfloat162(
        __float2bfloat16(x0 - __bfloat162float(h0)),
        __float2bfloat16(x1 - __bfloat162float(h1)));
    hi = *(uint32_t*)&hp;
    lo = *(uint32_t*)&lp;
}
__device__ __forceinline__ void split_store(__nv_bfloat16* dh, __nv_bfloat16* dl,
                                            size_t off, float v0, float v1) {
    uint32_t hi, lo;
    split_pair(v0, v1, hi, lo);
    *(uint32_t*)(dh + off) = hi;
    *(uint32_t*)(dl + off) = lo;
}

// ---------------------------------------------------------------------------
// convert x (fp32) -> g_xhi/g_xlo
// ---------------------------------------------------------------------------
__global__ __launch_bounds__(256) void convert_x(const float* __restrict__ src)
{
    int i = blockIdx.x * 256 + threadIdx.x;
    float4 v = ((const float4*)src)[i];
    split_store(g_xhi, g_xlo, (size_t)i * 4,     v.x, v.y);
    split_store(g_xhi, g_xlo, (size_t)i * 4 + 2, v.z, v.w);
}

// ---------------------------------------------------------------------------
// transpose + split weights: w [K=1024, N] -> wt hi/lo [N, K]
// W=0 -> w_attn (N=3072), W=1 -> w_proj (N=1024)
// ---------------------------------------------------------------------------
template<int W>
__global__ void transpose_split_k(const float* __restrict__ w)
{
    __nv_bfloat16* th = (W == 0) ? g_wqh : g_wph;
    __nv_bfloat16* tl = (W == 0) ? g_wql : g_wpl;
    const int N = (W == 0) ? N_QKV : CC;
    __shared__ float ts[32][33];
    int n0 = blockIdx.x * 32, k0 = blockIdx.y * 32;
    int tx = threadIdx.x, ty = threadIdx.y;   // (32, 8)
    #pragma unroll
    for (int i = 0; i < 32; i += 8)
        ts[ty + i][tx] = w[(size_t)(k0 + ty + i) * N + n0 + tx];
    __syncthreads();
    #pragma unroll
    for (int i = 0; i < 32; i += 8) {
        float v = ts[tx][ty + i];
        __nv_bfloat16 h = __float2bfloat16(v);
        size_t o = (size_t)(n0 + ty + i) * CC + k0 + tx;
        th[o] = h;
        tl[o] = __float2bfloat16(v - __bfloat162float(h));
    }
}

// ---------------------------------------------------------------------------
// mma.sync GEMM: C[128x128] = A[M,1024] @ B^T (B stored [N,1024]) + bias
// bf16x3 passes (AhBh + AhBl + AlBh), fp32 accum.
// EPI=0: A=x, B=w_attn^T -> scatter bf16 hi/lo q(*0.125)/k/v [B,H,T,64]
// EPI=1: A=attn, B=w_proj^T -> fp32 out
// smem per stage: Ah(10240) Al Bh Bl = 40960; 2 stages = 81920
// ---------------------------------------------------------------------------
#define GST 40960
template<int EPI>
__global__ __launch_bounds__(256) void mma_gemm(const float* __restrict__ bias,
                                                float* __restrict__ outp)
{
    const __nv_bfloat16* Ahi = (EPI == 0) ? g_xhi : g_ahi;
    const __nv_bfloat16* Alo = (EPI == 0) ? g_xlo : g_alo;
    const __nv_bfloat16* Bhi = (EPI == 0) ? g_wqh : g_wph;
    const __nv_bfloat16* Blo = (EPI == 0) ? g_wql : g_wpl;

    extern __shared__ char smc[];
    const uint32_t smb = smem_u32(smc);
    const int t = threadIdx.x, wid = t >> 5, l = t & 31;
    const int wm = wid >> 2, wn = wid & 3;     // 2 x 4 warps
    const int n0 = blockIdx.x * 128, m0 = blockIdx.y * 128;

    float acc[4][4][4];
    #pragma unroll
    for (int i = 0; i < 4; i++)
        #pragma unroll
        for (int j = 0; j < 4; j++)
            #pragma unroll
            for (int k = 0; k < 4; k++) acc[i][j][k] = 0.f;

    auto issue = [&](int s, int stg) {
        const int koff = s * 32;
        const uint32_t sb = smb + stg * GST;
        #pragma unroll
        for (int i = 0; i < 2; i++) {
            int c = 2 * t + i, row = c >> 2, q = c & 3;
            uint32_t so = (uint32_t)(row * 80 + q * 16);
            size_t ga = (size_t)(m0 + row) * CC + koff + q * 8;
            size_t gb = (size_t)(n0 + row) * CC + koff + q * 8;
            cpasync16(sb + so,         Ahi + ga);
            cpasync16(sb + 10240 + so, Alo + ga);
            cpasync16(sb + 20480 + so, Bhi + gb);
            cpasync16(sb + 30720 + so, Blo + gb);
        }
        CP_COMMIT();
    };

    issue(0, 0);
    for (int s = 0; s < 32; s++) {
        if (s < 31) { issue(s + 1, (s + 1) & 1); CP_WAIT(1); }
        else CP_WAIT(0);
        __syncthreads();
        const uint32_t sb = smb + (s & 1) * GST;
        #pragma unroll
        for (int ks = 0; ks < 2; ks++) {
            uint32_t ah[4][4], al[4][4];
            #pragma unroll
            for (int mt = 0; mt < 4; mt++) {
                uint32_t ad = sb + (uint32_t)((wm * 64 + mt * 16 + (l & 15)) * 80
                                              + ks * 32 + (l >> 4) * 16);
                ldsm4(ah[mt][0], ah[mt][1], ah[mt][2], ah[mt][3], ad);
                ldsm4(al[mt][0], al[mt][1], al[mt][2], al[mt][3], ad + 10240);
            }
            uint32_t bh[4][2], bl[4][2];
            #pragma unroll
            for (int j = 0; j < 2; j++) {
                uint32_t bd = sb + 20480
                    + (uint32_t)((wn * 32 + 16 * j + (l & 7) + ((l >> 4) & 1) * 8) * 80
                                 + ks * 32 + ((l >> 3) & 1) * 16);
                uint32_t r0, r1, r2, r3;
                ldsm4(r0, r1, r2, r3, bd);
                bh[2*j][0] = r0; bh[2*j][1] = r1; bh[2*j+1][0] = r2; bh[2*j+1][1] = r3;
                ldsm4(r0, r1, r2, r3, bd + 10240);
                bl[2*j][0] = r0; bl[2*j][1] = r1; bl[2*j+1][0] = r2; bl[2*j+1][1] = r3;
            }
            #pragma unroll
            for (int mt = 0; mt < 4; mt++)
                #pragma unroll
                for (int nt = 0; nt < 4; nt++) {
                    mma16816(acc[mt][nt], ah[mt], bh[nt][0], bh[nt][1]);
                    mma16816(acc[mt][nt], ah[mt], bl[nt][0], bl[nt][1]);
                    mma16816(acc[mt][nt], al[mt], bh[nt][0], bh[nt][1]);
                }
        }
        __syncthreads();
    }

    // epilogue
    #pragma unroll
    for (int mt = 0; mt < 4; mt++) {
        const int rA = m0 + wm * 64 + mt * 16 + (l >> 2);
        const int rB = rA + 8;
        #pragma unroll
        for (int nt = 0; nt < 4; nt++) {
            const int n = n0 + wn * 32 + nt * 8 + 2 * (l & 3);
            const float bi0 = bias[n], bi1 = bias[n + 1];
            float v0 = acc[mt][nt][0] + bi0, v1 = acc[mt][nt][1] + bi1;
            float v2 = acc[mt][nt][2] + bi0, v3 = acc[mt][nt][3] + bi1;
            if (EPI == 0) {
                const int which = n >> 10;
                const int h = (n & 1023) >> 6, d = n & 63;
                if (which == 0) { v0 *= 0.125f; v1 *= 0.125f; v2 *= 0.125f; v3 *= 0.125f; }
                __nv_bfloat16* dh = (which == 0) ? g_qh : (which == 1) ? g_kh : g_vh;
                __nv_bfloat16* dl = (which == 0) ? g_ql : (which == 1) ? g_kl : g_vl;
                const int bA = rA >> 11, tA = rA & 2047;
                const int bB = rB >> 11, tB = rB & 2047;
                split_store(dh, dl, (((size_t)(bA * NH + h)) * TT + tA) * HD + d, v0, v1);
                split_store(dh, dl, (((size_t)(bB * NH + h)) * TT + tB) * HD + d, v2, v3);
            } else {
                *(float2*)&outp[(size_t)rA * CC + n] = make_float2(v0, v1);
                *(float2*)&outp[(size_t)rB * CC + n] = make_float2(v2, v3);
            }
        }
    }
}

// ---------------------------------------------------------------------------
// Flash attention on mma.sync. Block: 128 thr (4 warps), 64-row q tile.
// smem: Qh@0 Ql@9216 | stages@18432 + stg*36864: Kh,Kl(+9216),Vh(+18432),Vl(+27648)
// rows padded to 144B (conflict-free ldmatrix / ldmatrix.trans).
// ---------------------------------------------------------------------------
#define FQ_OFF 0
#define FKV_OFF 18432
#define FKV_ST 36864
#define FLASH_SMEM (FKV_OFF + 2*FKV_ST)   // 92160

__global__ __launch_bounds__(128) void flash_mma()
{
    extern __shared__ char smc[];
    const uint32_t smb = smem_u32(smc);
    const int t = threadIdx.x, w = t >> 5, l = t & 31;
    const int qt = (int)gridDim.x - 1 - (int)blockIdx.x;   // heavy tiles first
    const int h = blockIdx.y, b = blockIdx.z;
    const size_t hoff = ((size_t)(b * NH + h)) * TT * HD;
    const int q0 = qt * 64;

    auto kvload = [&](int kt, int stg) {
        const uint32_t sb = smb + FKV_OFF + stg * FKV_ST;
        const int k0 = kt * 64;
        #pragma unroll
        for (int i = 0; i < 4; i++) {
            int c = t + i * 128, row = c >> 3, q = c & 7;
            uint32_t so = (uint32_t)(row * 144 + q * 16);
            size_t g = hoff + (size_t)(k0 + row) * HD + q * 8;
            cpasync16(sb + so,         g_kh + g);
            cpasync16(sb + 9216 + so,  g_kl + g);
            cpasync16(sb + 18432 + so, g_vh + g);
            cpasync16(sb + 27648 + so, g_vl + g);
        }
        CP_COMMIT();
    };

    // Q loads + stage0 KV in one group
    #pragma unroll
    for (int i = 0; i < 4; i++) {
        int c = t + i * 128, row = c >> 3, q = c & 7;
        uint32_t so = (uint32_t)(row * 144 + q * 16);
        size_t g = hoff + (size_t)(q0 + row) * HD + q * 8;
        cpasync16(smb + so,        g_qh + g);
        cpasync16(smb + 9216 + so, g_ql + g);
    }
    kvload(0, 0);

    float mA = -1e30f, mB = -1e30f, lA = 0.f, lB = 0.f;
    float o[8][4];
    #pragma unroll
    for (int j = 0; j < 8; j++)
        #pragma unroll
        for (int k = 0; k < 4; k++) o[j][k] = 0.f;

    uint32_t qh[4][4], ql[4][4];

    for (int kt = 0; kt <= qt; kt++) {
        if (kt < qt) { kvload(kt + 1, (kt + 1) & 1); CP_WAIT(1); }
        else CP_WAIT(0);
        __syncthreads();
        if (kt == 0) {
            #pragma unroll
            for (int ks = 0; ks < 4; ks++) {
                uint32_t ad = smb + (uint32_t)((w * 16 + (l & 15)) * 144
                                               + ks * 32 + (l >> 4) * 16);
                ldsm4(qh[ks][0], qh[ks][1], qh[ks][2], qh[ks][3], ad);
                ldsm4(ql[ks][0], ql[ks][1], ql[ks][2], ql[ks][3], ad + 9216);
            }
        }
        const uint32_t sb = smb + FKV_OFF + (kt & 1) * FKV_ST;

        // S = Q K^T (3-pass)
        float s[8][4];
        #pragma unroll
        for (int j = 0; j < 8; j++)
            #pragma unroll
            for (int k = 0; k < 4; k++) s[j][k] = 0.f;
        #pragma unroll
        for (int ks = 0; ks < 4; ks++) {
            #pragma unroll
            for (int j = 0; j < 4; j++) {
                uint32_t kd = sb + (uint32_t)((16 * j + (l & 7) + ((l >> 4) & 1) * 8) * 144
                                              + ks * 32 + ((l >> 3) & 1) * 16);
                uint32_t r0, r1, r2, r3, u0, u1, u2, u3;
                ldsm4(r0, r1, r2, r3, kd);
                ldsm4(u0, u1, u2, u3, kd + 9216);
                mma16816(s[2*j],   qh[ks], r0, r1);
                mma16816(s[2*j+1], qh[ks], r2, r3);
                mma16816(s[2*j],   qh[ks], u0, u1);
                mma16816(s[2*j+1], qh[ks], u2, u3);
                mma16816(s[2*j],   ql[ks], r0, r1);
                mma16816(s[2*j+1], ql[ks], r2, r3);
            }
        }

        const int rA = q0 + w * 16 + (l >> 2), rB = rA + 8;
        if (kt == qt) {
            const int cb = 2 * (l & 3);
            #pragma unroll
            for (int j = 0; j < 8; j++) {
                int cg = kt * 64 + 8 * j + cb;
                if (cg     > rA) s[j][0] = -1e30f;
                if (cg + 1 > rA) s[j][1] = -1e30f;
                if (cg     > rB) s[j][2] = -1e30f;
                if (cg + 1 > rB) s[j][3] = -1e30f;
            }
        }

        // online softmax
        float mxA = -1e30f, mxB = -1e30f;
        #pragma unroll
        for (int j = 0; j < 8; j++) {
            mxA = fmaxf(mxA, fmaxf(s[j][0], s[j][1]));
            mxB = fmaxf(mxB, fmaxf(s[j][2], s[j][3]));
        }
        mxA = fmaxf(mxA, __shfl_xor_sync(0xffffffffu, mxA, 1));
        mxA = fmaxf(mxA, __shfl_xor_sync(0xffffffffu, mxA, 2));
        mxB = fmaxf(mxB, __shfl_xor_sync(0xffffffffu, mxB, 1));
        mxB = fmaxf(mxB, __shfl_xor_sync(0xffffffffu, mxB, 2));
        const float nmA = fmaxf(mA, mxA), nmB = fmaxf(mB, mxB);
        const float aA = __expf(mA - nmA), aB = __expf(mB - nmB);
        mA = nmA; mB = nmB;
        float suA = 0.f, suB = 0.f;
        #pragma unroll
        for (int j = 0; j < 8; j++) {
            s[j][0] = __expf(s[j][0] - mA);
            s[j][1] = __expf(s[j][1] - mA);
            s[j][2] = __expf(s[j][2] - mB);
            s[j][3] = __expf(s[j][3] - mB);
            suA += s[j][0] + s[j][1];
            suB += s[j][2] + s[j][3];
        }
        suA += __shfl_xor_sync(0xffffffffu, suA, 1);
        suA += __shfl_xor_sync(0xffffffffu, suA, 2);
        suB += __shfl_xor_sync(0xffffffffu, suB, 1);
        suB += __shfl_xor_sync(0xffffffffu, suB, 2);
        lA = lA * aA + suA;
        lB = lB * aB + suB;
        #pragma unroll
        for (int j = 0; j < 8; j++) {
            o[j][0] *= aA; o[j][1] *= aA; o[j][2] *= aB; o[j][3] *= aB;
        }

        // O += P V (3-pass; V via ldmatrix.trans)
        #pragma unroll
        for (int ks = 0; ks < 4; ks++) {
            uint32_t pa[4], pb[4];
            split_pair(s[2*ks][0],   s[2*ks][1],   pa[0], pb[0]);
            split_pair(s[2*ks][2],   s[2*ks][3],   pa[1], pb[1]);
            split_pair(s[2*ks+1][0], s[2*ks+1][1], pa[2], pb[2]);
            split_pair(s[2*ks+1][2], s[2*ks+1][3], pa[3], pb[3]);
            #pragma unroll
            for (int j = 0; j < 4; j++) {
                uint32_t vd = sb + 18432
                    + (uint32_t)((ks * 16 + (l & 7) + ((l >> 3) & 1) * 8) * 144
                                 + 32 * j + ((l >> 4) & 1) * 16);
                uint32_t r0, r1, r2, r3, u0, u1, u2, u3;
                ldsm4t(r0, r1, r2, r3, vd);
                ldsm4t(u0, u1, u2, u3, vd + 9216);
                mma16816(o[2*j],   pa, r0, r1);
                mma16816(o[2*j+1], pa, r2, r3);
                mma16816(o[2*j],   pa, u0, u1);
                mma16816(o[2*j+1], pa, u2, u3);
                mma16816(o[2*j],   pb, r0, r1);
                mma16816(o[2*j+1], pb, r2, r3);
            }
        }
        __syncthreads();
    }

    const float iA = 1.f / lA, iB = 1.f / lB;
    const int rA = q0 + w * 16 + (l >> 2), rB = rA + 8;
    const size_t baseA = ((size_t)(b * TT + rA)) * CC + h * HD;
    const size_t baseB = ((size_t)(b * TT + rB)) * CC + h * HD;
    #pragma unroll
    for (int j = 0; j < 8; j++) {
        const int d = 8 * j + 2 * (l & 3);
        split_store(g_ahi, g_alo, baseA + d, o[j][0] * iA, o[j][1] * iA);
        split_store(g_ahi, g_alo, baseB + d, o[j][2] * iB, o[j][3] * iB);
    }
}

// ---------------------------------------------------------------------------
extern "C" void kernel_launch(void* const* d_in, const int* in_sizes, int n_in,
                              void* d_out, int out_size)
{
    const float* x      = (const float*)d_in[0];
    const float* w_attn = (const float*)d_in[1];
    const float* b_attn = (const float*)d_in[2];
    const float* w_proj = (const float*)d_in[3];
    const float* b_proj = (const float*)d_in[4];
    float* out = (float*)d_out;

    cudaFuncSetAttribute(mma_gemm<0>, cudaFuncAttributeMaxDynamicSharedMemorySize, 2 * GST);
    cudaFuncSetAttribute(mma_gemm<1>, cudaFuncAttributeMaxDynamicSharedMemorySize, 2 * GST);
    cudaFuncSetAttribute(flash_mma, cudaFuncAttributeMaxDynamicSharedMemorySize, FLASH_SMEM);

    convert_x<<<M1 * CC / 1024, 256>>>(x);
    transpose_split_k<0><<<dim3(N_QKV / 32, CC / 32), dim3(32, 8)>>>(w_attn);
    transpose_split_k<1><<<dim3(CC / 32, CC / 32), dim3(32, 8)>>>(w_proj);

    mma_gemm<0><<<dim3(N_QKV / 128, M1 / 128), 256, 2 * GST>>>(b_attn, nullptr);
    flash_mma<<<dim3(TT / 64, NH, BB), 128, FLASH_SMEM>>>();
    mma_gemm<1><<<dim3(CC / 128, M1 / 128), 256, 2 * GST>>>(b_proj, out);
}

// round 4
// speedup vs baseline: 7.0057x; 1.5655x over previous
#include <cuda_runtime.h>
#include <cuda_fp16.h>
#include <cstdint>
#include <math.h>

#define BB 4
#define TT 2048
#define CC 1024
#define NH 16
#define HD 64
#define M1 (BB*TT)          // 8192
#define N_QKV (3*CC)        // 3072

// ---------------------------------------------------------------------------
// Device-global scratch (allocation-free rule). fp16 hi/lo scheme:
//   A-side operands keep hi+lo; B-side operands hi only (2-pass split).
// ---------------------------------------------------------------------------
__device__ __half g_xhi[M1*CC], g_xlo[M1*CC];     // x [M,K] hi+lo
__device__ __half g_wqh[N_QKV*CC];                // w_attn^T [N,K] hi
__device__ __half g_wph[CC*CC];                   // w_proj^T [N,K] hi
__device__ __half g_qh[BB*NH*TT*HD], g_ql[BB*NH*TT*HD];  // q hi+lo (A of S)
__device__ __half g_kh[BB*NH*TT*HD];              // k hi (B of S)
__device__ __half g_vh[BB*NH*TT*HD];              // v hi (B of PV)
__device__ __half g_ahi[M1*CC], g_alo[M1*CC];     // attn out hi+lo (A of proj)

// ---------------------------------------------------------------------------
// PTX helpers (baseline ISA: ldmatrix / mma.sync / cp.async)
// ---------------------------------------------------------------------------
__device__ __forceinline__ uint32_t smem_u32(const void* p) {
    uint32_t a;
    asm("{ .reg .u64 t; cvta.to.shared.u64 t, %1; cvt.u32.u64 %0, t; }"
        : "=r"(a) : "l"(p));
    return a;
}
__device__ __forceinline__ void cpasync16(uint32_t dst, const void* src) {
    asm volatile("cp.async.cg.shared.global [%0], [%1], 16;"
                 :: "r"(dst), "l"(src) : "memory");
}
#define CP_COMMIT() asm volatile("cp.async.commit_group;" ::: "memory")
#define CP_WAIT(N)  asm volatile("cp.async.wait_group %0;" :: "n"(N) : "memory")

__device__ __forceinline__ void ldsm4(uint32_t& r0, uint32_t& r1, uint32_t& r2,
                                      uint32_t& r3, uint32_t a) {
    asm volatile("ldmatrix.sync.aligned.m8n8.x4.shared.b16 {%0,%1,%2,%3},[%4];"
                 : "=r"(r0), "=r"(r1), "=r"(r2), "=r"(r3) : "r"(a));
}
__device__ __forceinline__ void ldsm4t(uint32_t& r0, uint32_t& r1, uint32_t& r2,
                                       uint32_t& r3, uint32_t a) {
    asm volatile("ldmatrix.sync.aligned.m8n8.x4.trans.shared.b16 {%0,%1,%2,%3},[%4];"
                 : "=r"(r0), "=r"(r1), "=r"(r2), "=r"(r3) : "r"(a));
}
__device__ __forceinline__ void mma16816(float* c, const uint32_t* a,
                                         uint32_t b0, uint32_t b1) {
    asm volatile("mma.sync.aligned.m16n8k16.row.col.f32.f16.f16.f32 "
                 "{%0,%1,%2,%3},{%4,%5,%6,%7},{%8,%9},{%0,%1,%2,%3};"
                 : "+f"(c[0]), "+f"(c[1]), "+f"(c[2]), "+f"(c[3])
                 : "r"(a[0]), "r"(a[1]), "r"(a[2]), "r"(a[3]), "r"(b0), "r"(b1));
}

__device__ __forceinline__ void split_pair(float x0, float x1,
                                           uint32_t& hi, uint32_t& lo) {
    __half h0 = __float2half(x0), h1 = __float2half(x1);
    __half2 hp = __halves2half2(h0, h1);
    __half2 lp = __halves2half2(__float2half(x0 - __half2float(h0)),
                                __float2half(x1 - __half2float(h1)));
    hi = *(uint32_t*)&hp;
    lo = *(uint32_t*)&lp;
}
__device__ __forceinline__ void split_store(__half* dh, __half* dl,
                                            size_t off, float v0, float v1) {
    uint32_t hi, lo;
    split_pair(v0, v1, hi, lo);
    *(uint32_t*)(dh + off) = hi;
    *(uint32_t*)(dl + off) = lo;
}
__device__ __forceinline__ void hi_store(__half* dh, size_t off, float v0, float v1) {
    __half2 hp = __halves2half2(__float2half(v0), __float2half(v1));
    *(uint32_t*)(dh + off) = *(uint32_t*)&hp;
}

// ---------------------------------------------------------------------------
// convert x (fp32) -> g_xhi/g_xlo
// ---------------------------------------------------------------------------
__global__ __launch_bounds__(256) void convert_x(const float* __restrict__ src)
{
    int i = blockIdx.x * 256 + threadIdx.x;
    float4 v = ((const float4*)src)[i];
    split_store(g_xhi, g_xlo, (size_t)i * 4,     v.x, v.y);
    split_store(g_xhi, g_xlo, (size_t)i * 4 + 2, v.z, v.w);
}

// ---------------------------------------------------------------------------
// transpose weights: w [K=1024, N] -> wt hi [N, K]   (hi only)
// ---------------------------------------------------------------------------
template<int W>
__global__ void transpose_w(const float* __restrict__ w)
{
    __half* th = (W == 0) ? g_wqh : g_wph;
    const int N = (W == 0) ? N_QKV : CC;
    __shared__ float ts[32][33];
    int n0 = blockIdx.x * 32, k0 = blockIdx.y * 32;
    int tx = threadIdx.x, ty = threadIdx.y;   // (32, 8)
    #pragma unroll
    for (int i = 0; i < 32; i += 8)
        ts[ty + i][tx] = w[(size_t)(k0 + ty + i) * N + n0 + tx];
    __syncthreads();
    #pragma unroll
    for (int i = 0; i < 32; i += 8)
        th[(size_t)(n0 + ty + i) * CC + k0 + tx] = __float2half(ts[tx][ty + i]);
}

// ---------------------------------------------------------------------------
// mma.sync GEMM: C[128x128] = A[M,1024] @ B^T (B stored [N,1024]) + bias
// fp16 2-pass (Ah*Bh + Al*Bh), fp32 accum.
// smem per stage: Ah(10240) Al(10240) Bh(10240) = 30720; 3 stages.
// EPI=0: scatter q(hi/lo, *0.125) / k(hi) / v(hi) into [B,H,T,64]
// EPI=1: fp32 out row-major
// ---------------------------------------------------------------------------
#define GST 30720
#define GSMEM (3*GST)   // 92160

template<int EPI>
__global__ __launch_bounds__(256, 2) void mma_gemm(const float* __restrict__ bias,
                                                   float* __restrict__ outp)
{
    const __half* Ahi = (EPI == 0) ? g_xhi : g_ahi;
    const __half* Alo = (EPI == 0) ? g_xlo : g_alo;
    const __half* Bhi = (EPI == 0) ? g_wqh : g_wph;

    extern __shared__ char smc[];
    const uint32_t smb = smem_u32(smc);
    const int t = threadIdx.x, wid = t >> 5, l = t & 31;
    const int wm = wid >> 2, wn = wid & 3;     // 2 x 4 warps, 64x32 warp tile
    const int n0 = blockIdx.x * 128, m0 = blockIdx.y * 128;

    float acc[4][4][4];
    #pragma unroll
    for (int i = 0; i < 4; i++)
        #pragma unroll
        for (int j = 0; j < 4; j++)
            #pragma unroll
            for (int k = 0; k < 4; k++) acc[i][j][k] = 0.f;

    auto issue = [&](int s) {
        const int koff = s * 32;
        const uint32_t sb = smb + (s % 3) * GST;
        #pragma unroll
        for (int i = 0; i < 2; i++) {
            int c = 2 * t + i, row = c >> 2, q = c & 3;
            uint32_t so = (uint32_t)(row * 80 + q * 16);
            size_t ga = (size_t)(m0 + row) * CC + koff + q * 8;
            size_t gb = (size_t)(n0 + row) * CC + koff + q * 8;
            cpasync16(sb + so,         Ahi + ga);
            cpasync16(sb + 10240 + so, Alo + ga);
            cpasync16(sb + 20480 + so, Bhi + gb);
        }
        CP_COMMIT();
    };

    issue(0);
    issue(1);
    for (int s = 0; s < 32; s++) {
        CP_WAIT(1);
        __syncthreads();
        if (s + 2 < 32) issue(s + 2);
        const uint32_t sb = smb + (s % 3) * GST;
        #pragma unroll
        for (int ks = 0; ks < 2; ks++) {
            uint32_t ah[4][4], al[4][4];
            #pragma unroll
            for (int mt = 0; mt < 4; mt++) {
                uint32_t ad = sb + (uint32_t)((wm * 64 + mt * 16 + (l & 15)) * 80
                                              + ks * 32 + (l >> 4) * 16);
                ldsm4(ah[mt][0], ah[mt][1], ah[mt][2], ah[mt][3], ad);
                ldsm4(al[mt][0], al[mt][1], al[mt][2], al[mt][3], ad + 10240);
            }
            uint32_t bh[4][2];
            #pragma unroll
            for (int j = 0; j < 2; j++) {
                uint32_t bd = sb + 20480
                    + (uint32_t)((wn * 32 + 16 * j + (l & 7) + ((l >> 4) & 1) * 8) * 80
                                 + ks * 32 + ((l >> 3) & 1) * 16);
                uint32_t r0, r1, r2, r3;
                ldsm4(r0, r1, r2, r3, bd);
                bh[2*j][0] = r0; bh[2*j][1] = r1; bh[2*j+1][0] = r2; bh[2*j+1][1] = r3;
            }
            #pragma unroll
            for (int mt = 0; mt < 4; mt++)
                #pragma unroll
                for (int nt = 0; nt < 4; nt++) {
                    mma16816(acc[mt][nt], ah[mt], bh[nt][0], bh[nt][1]);
                    mma16816(acc[mt][nt], al[mt], bh[nt][0], bh[nt][1]);
                }
        }
        __syncthreads();
    }

    // epilogue
    #pragma unroll
    for (int mt = 0; mt < 4; mt++) {
        const int rA = m0 + wm * 64 + mt * 16 + (l >> 2);
        const int rB = rA + 8;
        #pragma unroll
        for (int nt = 0; nt < 4; nt++) {
            const int n = n0 + wn * 32 + nt * 8 + 2 * (l & 3);
            const float bi0 = bias[n], bi1 = bias[n + 1];
            float v0 = acc[mt][nt][0] + bi0, v1 = acc[mt][nt][1] + bi1;
            float v2 = acc[mt][nt][2] + bi0, v3 = acc[mt][nt][3] + bi1;
            if (EPI == 0) {
                const int which = n >> 10;
                const int h = (n & 1023) >> 6, d = n & 63;
                const int bA = rA >> 11, tA = rA & 2047;
                const int bB = rB >> 11, tB = rB & 2047;
                const size_t oA = (((size_t)(bA * NH + h)) * TT + tA) * HD + d;
                const size_t oB = (((size_t)(bB * NH + h)) * TT + tB) * HD + d;
                if (which == 0) {
                    split_store(g_qh, g_ql, oA, v0 * 0.125f, v1 * 0.125f);
                    split_store(g_qh, g_ql, oB, v2 * 0.125f, v3 * 0.125f);
                } else if (which == 1) {
                    hi_store(g_kh, oA, v0, v1);
                    hi_store(g_kh, oB, v2, v3);
                } else {
                    hi_store(g_vh, oA, v0, v1);
                    hi_store(g_vh, oB, v2, v3);
                }
            } else {
                *(float2*)&outp[(size_t)rA * CC + n] = make_float2(v0, v1);
                *(float2*)&outp[(size_t)rB * CC + n] = make_float2(v2, v3);
            }
        }
    }
}

// ---------------------------------------------------------------------------
// Flash attention on mma.sync (fp16 2-pass). 128 thr, 64-row q tile.
// smem: Qh@0 (9216) Ql@9216 | stages@18432 + stg*18432: Kh@0, Vh@9216
// rows padded to 144B.
// ---------------------------------------------------------------------------
#define FKV_OFF 18432
#define FKV_ST 18432
#define FLASH_SMEM (FKV_OFF + 2*FKV_ST)   // 55296

__global__ __launch_bounds__(128) void flash_mma()
{
    extern __shared__ char smc[];
    const uint32_t smb = smem_u32(smc);
    const int t = threadIdx.x, w = t >> 5, l = t & 31;
    const int qt = (int)gridDim.x - 1 - (int)blockIdx.x;   // heavy tiles first
    const int h = blockIdx.y, b = blockIdx.z;
    const size_t hoff = ((size_t)(b * NH + h)) * TT * HD;
    const int q0 = qt * 64;

    auto kvload = [&](int kt, int stg) {
        const uint32_t sb = smb + FKV_OFF + stg * FKV_ST;
        const int k0 = kt * 64;
        #pragma unroll
        for (int i = 0; i < 4; i++) {
            int c = t + i * 128, row = c >> 3, q = c & 7;
            uint32_t so = (uint32_t)(row * 144 + q * 16);
            size_t g = hoff + (size_t)(k0 + row) * HD + q * 8;
            cpasync16(sb + so,        g_kh + g);
            cpasync16(sb + 9216 + so, g_vh + g);
        }
        CP_COMMIT();
    };

    #pragma unroll
    for (int i = 0; i < 4; i++) {
        int c = t + i * 128, row = c >> 3, q = c & 7;
        uint32_t so = (uint32_t)(row * 144 + q * 16);
        size_t g = hoff + (size_t)(q0 + row) * HD + q * 8;
        cpasync16(smb + so,        g_qh + g);
        cpasync16(smb + 9216 + so, g_ql + g);
    }
    kvload(0, 0);

    float mA = -1e30f, mB = -1e30f, lA = 0.f, lB = 0.f;
    float o[8][4];
    #pragma unroll
    for (int j = 0; j < 8; j++)
        #pragma unroll
        for (int k = 0; k < 4; k++) o[j][k] = 0.f;

    uint32_t qh[4][4], ql[4][4];

    for (int kt = 0; kt <= qt; kt++) {
        if (kt < qt) { kvload(kt + 1, (kt + 1) & 1); CP_WAIT(1); }
        else CP_WAIT(0);
        __syncthreads();
        if (kt == 0) {
            #pragma unroll
            for (int ks = 0; ks < 4; ks++) {
                uint32_t ad = smb + (uint32_t)((w * 16 + (l & 15)) * 144
                                               + ks * 32 + (l >> 4) * 16);
                ldsm4(qh[ks][0], qh[ks][1], qh[ks][2], qh[ks][3], ad);
                ldsm4(ql[ks][0], ql[ks][1], ql[ks][2], ql[ks][3], ad + 9216);
            }
        }
        const uint32_t sb = smb + FKV_OFF + (kt & 1) * FKV_ST;

        // S = Q K^T  (2-pass: Qh*K + Ql*K)
        float s[8][4];
        #pragma unroll
        for (int j = 0; j < 8; j++)
            #pragma unroll
            for (int k = 0; k < 4; k++) s[j][k] = 0.f;
        #pragma unroll
        for (int ks = 0; ks < 4; ks++) {
            #pragma unroll
            for (int j = 0; j < 4; j++) {
                uint32_t kd = sb + (uint32_t)((16 * j + (l & 7) + ((l >> 4) & 1) * 8) * 144
                                              + ks * 32 + ((l >> 3) & 1) * 16);
                uint32_t r0, r1, r2, r3;
                ldsm4(r0, r1, r2, r3, kd);
                mma16816(s[2*j],   qh[ks], r0, r1);
                mma16816(s[2*j],   ql[ks], r0, r1);
                mma16816(s[2*j+1], qh[ks], r2, r3);
                mma16816(s[2*j+1], ql[ks], r2, r3);
            }
        }

        const int rA = q0 + w * 16 + (l >> 2), rB = rA + 8;
        if (kt == qt) {
            const int cb = 2 * (l & 3);
            #pragma unroll
            for (int j = 0; j < 8; j++) {
                int cg = kt * 64 + 8 * j + cb;
                if (cg     > rA) s[j][0] = -1e30f;
                if (cg + 1 > rA) s[j][1] = -1e30f;
                if (cg     > rB) s[j][2] = -1e30f;
                if (cg + 1 > rB) s[j][3] = -1e30f;
            }
        }

        // online softmax
        float mxA = -1e30f, mxB = -1e30f;
        #pragma unroll
        for (int j = 0; j < 8; j++) {
            mxA = fmaxf(mxA, fmaxf(s[j][0], s[j][1]));
            mxB = fmaxf(mxB, fmaxf(s[j][2], s[j][3]));
        }
        mxA = fmaxf(mxA, __shfl_xor_sync(0xffffffffu, mxA, 1));
        mxA = fmaxf(mxA, __shfl_xor_sync(0xffffffffu, mxA, 2));
        mxB = fmaxf(mxB, __shfl_xor_sync(0xffffffffu, mxB, 1));
        mxB = fmaxf(mxB, __shfl_xor_sync(0xffffffffu, mxB, 2));
        const float nmA = fmaxf(mA, mxA), nmB = fmaxf(mB, mxB);
        const float aA = __expf(mA - nmA), aB = __expf(mB - nmB);
        mA = nmA; mB = nmB;
        float suA = 0.f, suB = 0.f;
        #pragma unroll
        for (int j = 0; j < 8; j++) {
            s[j][0] = __expf(s[j][0] - mA);
            s[j][1] = __expf(s[j][1] - mA);
            s[j][2] = __expf(s[j][2] - mB);
            s[j][3] = __expf(s[j][3] - mB);
            suA += s[j][0] + s[j][1];
            suB += s[j][2] + s[j][3];
        }
        suA += __shfl_xor_sync(0xffffffffu, suA, 1);
        suA += __shfl_xor_sync(0xffffffffu, suA, 2);
        suB += __shfl_xor_sync(0xffffffffu, suB, 1);
        suB += __shfl_xor_sync(0xffffffffu, suB, 2);
        lA = lA * aA + suA;
        lB = lB * aB + suB;
        #pragma unroll
        for (int j = 0; j < 8; j++) {
            o[j][0] *= aA; o[j][1] *= aA; o[j][2] *= aB; o[j][3] *= aB;
        }

        // O += P V  (2-pass: Ph*V + Pl*V; V hi via ldmatrix.trans)
        #pragma unroll
        for (int ks = 0; ks < 4; ks++) {
            uint32_t pa[4], pb[4];
            split_pair(s[2*ks][0],   s[2*ks][1],   pa[0], pb[0]);
            split_pair(s[2*ks][2],   s[2*ks][3],   pa[1], pb[1]);
            split_pair(s[2*ks+1][0], s[2*ks+1][1], pa[2], pb[2]);
            split_pair(s[2*ks+1][2], s[2*ks+1][3], pa[3], pb[3]);
            #pragma unroll
            for (int j = 0; j < 4; j++) {
                uint32_t vd = sb + 9216
                    + (uint32_t)((ks * 16 + (l & 7) + ((l >> 3) & 1) * 8) * 144
                                 + 32 * j + ((l >> 4) & 1) * 16);
                uint32_t r0, r1, r2, r3;
                ldsm4t(r0, r1, r2, r3, vd);
                mma16816(o[2*j],   pa, r0, r1);
                mma16816(o[2*j],   pb, r0, r1);
                mma16816(o[2*j+1], pa, r2, r3);
                mma16816(o[2*j+1], pb, r2, r3);
            }
        }
        __syncthreads();
    }

    const float iA = 1.f / lA, iB = 1.f / lB;
    const int rA = q0 + w * 16 + (l >> 2), rB = rA + 8;
    const size_t baseA = ((size_t)(b * TT + rA)) * CC + h * HD;
    const size_t baseB = ((size_t)(b * TT + rB)) * CC + h * HD;
    #pragma unroll
    for (int j = 0; j < 8; j++) {
        const int d = 8 * j + 2 * (l & 3);
        split_store(g_ahi, g_alo, baseA + d, o[j][0] * iA, o[j][1] * iA);
        split_store(g_ahi, g_alo, baseB + d, o[j][2] * iB, o[j][3] * iB);
    }
}

// ---------------------------------------------------------------------------
extern "C" void kernel_launch(void* const* d_in, const int* in_sizes, int n_in,
                              void* d_out, int out_size)
{
    const float* x      = (const float*)d_in[0];
    const float* w_attn = (const float*)d_in[1];
    const float* b_attn = (const float*)d_in[2];
    const float* w_proj = (const float*)d_in[3];
    const float* b_proj = (const float*)d_in[4];
    float* out = (float*)d_out;

    cudaFuncSetAttribute(mma_gemm<0>, cudaFuncAttributeMaxDynamicSharedMemorySize, GSMEM);
    cudaFuncSetAttribute(mma_gemm<1>, cudaFuncAttributeMaxDynamicSharedMemorySize, GSMEM);
    cudaFuncSetAttribute(flash_mma, cudaFuncAttributeMaxDynamicSharedMemorySize, FLASH_SMEM);

    convert_x<<<M1 * CC / 1024, 256>>>(x);
    transpose_w<0><<<dim3(N_QKV / 32, CC / 32), dim3(32, 8)>>>(w_attn);
    transpose_w<1><<<dim3(CC / 32, CC / 32), dim3(32, 8)>>>(w_proj);

    mma_gemm<0><<<dim3(N_QKV / 128, M1 / 128), 256, GSMEM>>>(b_attn, nullptr);
    flash_mma<<<dim3(TT / 64, NH, BB), 128, FLASH_SMEM>>>();
    mma_gemm<1><<<dim3(CC / 128, M1 / 128), 256, GSMEM>>>(b_proj, out);
}